// round 7
// baseline (speedup 1.0000x reference)
#include <cuda_runtime.h>
#include <math.h>

#define NB    1024
#define SIN   256
#define SPR   128
#define HIDN  512

// 1/sqrt(3) * log2(e): fold scores into exp2 domain
#define C_SCALE 0.83294064f
// log2(e): additive causal "mask" of +1.0 in exp2 domain
#define L2E 1.4426950408889634f

typedef unsigned long long u64;

struct Params {
    const float* X;           const float* T;
    const float* enc_in_w;    const float* enc_in_b;
    const float* enc_out_w;   const float* enc_out_b;
    const float* enc_ln1_w;   const float* enc_ln1_b;
    const float* enc_lin1_w;  const float* enc_lin1_b;
    const float* enc_lin2_w;  const float* enc_lin2_b;
    const float* enc_ln2_w;   const float* enc_ln2_b;
    const float* dec_a1_in_w; const float* dec_a1_in_b;
    const float* dec_a1_out_w;const float* dec_a1_out_b;
    const float* dec_ln1_w;   const float* dec_ln1_b;
    const float* dec_a2_in_w; const float* dec_a2_in_b;
    const float* dec_a2_out_w;const float* dec_a2_out_b;
    const float* dec_lin1_w;  const float* dec_lin1_b;
    const float* dec_lin2_w;  const float* dec_lin2_b;
    const float* dec_ln3_w;   const float* dec_ln3_b;
    float* out;
};

__device__ __forceinline__ float ex2f(float x) {
    float y; asm("ex2.approx.ftz.f32 %0, %1;" : "=f"(y) : "f"(x)); return y;
}
__device__ __forceinline__ float rcpf(float x) {
    float y; asm("rcp.approx.ftz.f32 %0, %1;" : "=f"(y) : "f"(x)); return y;
}

// ---- packed f32x2 ops (Blackwell) ----
__device__ __forceinline__ u64 fma2(u64 a, u64 b, u64 c) {
    u64 d; asm("fma.rn.f32x2 %0, %1, %2, %3;" : "=l"(d) : "l"(a), "l"(b), "l"(c)); return d;
}
__device__ __forceinline__ u64 mul2(u64 a, u64 b) {
    u64 d; asm("mul.rn.f32x2 %0, %1, %2;" : "=l"(d) : "l"(a), "l"(b)); return d;
}
__device__ __forceinline__ u64 add2(u64 a, u64 b) {
    u64 d; asm("add.rn.f32x2 %0, %1, %2;" : "=l"(d) : "l"(a), "l"(b)); return d;
}
__device__ __forceinline__ u64 pack2(float lo, float hi) {
    u64 d; asm("mov.b64 %0, {%1, %2};" : "=l"(d) : "f"(lo), "f"(hi)); return d;
}
__device__ __forceinline__ void unpack2(u64 d, float& a, float& b) {
    asm("mov.b64 {%0, %1}, %2;" : "=f"(a), "=f"(b) : "l"(d));
}

// One packed attention step: 2 keys vs 1 query. l folded into packed add.
__device__ __forceinline__ void qstep(u64 q0p, u64 q1p, u64 q2p,
                                      u64 xp, u64 yp, u64 zp,
                                      u64& aX, u64& aY, u64& aZ, u64& aL) {
    u64 d = fma2(q2p, zp, fma2(q1p, yp, mul2(q0p, xp)));
    float s0, s1; unpack2(d, s0, s1);
    u64 pp = pack2(ex2f(s0), ex2f(s1));
    aX = fma2(pp, xp, aX);
    aY = fma2(pp, yp, aY);
    aZ = fma2(pp, zp, aZ);
    aL = add2(aL, pp);
}
// Masked variant: reference ADDS tril(ones) to scores -> +log2(e) in exp2 domain.
__device__ __forceinline__ void qstep_m(u64 q0p, u64 q1p, u64 q2p,
                                        u64 xp, u64 yp, u64 zp,
                                        int j, int row,
                                        u64& aX, u64& aY, u64& aZ, u64& aL) {
    u64 d = fma2(q2p, zp, fma2(q1p, yp, mul2(q0p, xp)));
    float s0, s1; unpack2(d, s0, s1);
    s0 += (j     <= row) ? L2E : 0.f;
    s1 += (j + 1 <= row) ? L2E : 0.f;
    u64 pp = pack2(ex2f(s0), ex2f(s1));
    aX = fma2(pp, xp, aX);
    aY = fma2(pp, yp, aY);
    aZ = fma2(pp, zp, aZ);
    aL = add2(aL, pp);
}
__device__ __forceinline__ void hsum4(u64 aX, u64 aY, u64 aZ, u64 aL,
                                      float& x, float& y, float& z, float& l) {
    float a, b;
    unpack2(aX, a, b); x = a + b;
    unpack2(aY, a, b); y = a + b;
    unpack2(aZ, a, b); z = a + b;
    unpack2(aL, a, b); l = a + b;
}

// Fused two-value block reduction (2 barriers).
__device__ __forceinline__ void block_sum2(float& a, float& b, float* red) {
    #pragma unroll
    for (int o = 16; o; o >>= 1) {
        a += __shfl_xor_sync(0xffffffffu, a, o);
        b += __shfl_xor_sync(0xffffffffu, b, o);
    }
    int w = threadIdx.x >> 5;
    if ((threadIdx.x & 31) == 0) { red[w] = a; red[8 + w] = b; }
    __syncthreads();
    if (threadIdx.x < 16) {
        float x = red[threadIdx.x];
        x += __shfl_xor_sync(0x0000ffffu, x, 4);
        x += __shfl_xor_sync(0x0000ffffu, x, 2);
        x += __shfl_xor_sync(0x0000ffffu, x, 1);
        if ((threadIdx.x & 7) == 0) red[16 + (threadIdx.x >> 3)] = x;
    }
    __syncthreads();
    a = red[16]; b = red[17];
}

// LN over nrows*3 elems jointly; var = E[x^2]-mean^2 single pass.
__device__ __forceinline__ void layer_norm(const float* src, float* dst, int nrows,
                                           float inv_n, const float* w, const float* bb,
                                           float* red) {
    int t = threadIdx.x;
    float x0 = 0.f, x1 = 0.f, x2 = 0.f;
    if (t < nrows) { x0 = src[t*3]; x1 = src[t*3+1]; x2 = src[t*3+2]; }
    float s1 = x0 + x1 + x2;
    float s2 = fmaf(x0, x0, fmaf(x1, x1, x2 * x2));
    block_sum2(s1, s2, red);
    float mean = s1 * inv_n;
    float var  = fmaf(-mean, mean, s2 * inv_n);
    float rs = rsqrtf(var + 1e-5f);
    if (t < nrows) {
        dst[t*3+0] = (x0 - mean) * rs * w[t*3+0] + bb[t*3+0];
        dst[t*3+1] = (x1 - mean) * rs * w[t*3+1] + bb[t*3+1];
        dst[t*3+2] = (x2 - mean) * rs * w[t*3+2] + bb[t*3+2];
    }
    __syncthreads();
}

// LN writing into SoA arrays (for cross-attn keys).
__device__ __forceinline__ void layer_norm_soa(const float* src,
                                               float* dX, float* dY, float* dZ, int nrows,
                                               float inv_n, const float* w, const float* bb,
                                               float* red) {
    int t = threadIdx.x;
    float x0 = 0.f, x1 = 0.f, x2 = 0.f;
    if (t < nrows) { x0 = src[t*3]; x1 = src[t*3+1]; x2 = src[t*3+2]; }
    float s1 = x0 + x1 + x2;
    float s2 = fmaf(x0, x0, fmaf(x1, x1, x2 * x2));
    block_sum2(s1, s2, red);
    float mean = s1 * inv_n;
    float var  = fmaf(-mean, mean, s2 * inv_n);
    float rs = rsqrtf(var + 1e-5f);
    if (t < nrows) {
        dX[t] = (x0 - mean) * rs * w[t*3+0] + bb[t*3+0];
        dY[t] = (x1 - mean) * rs * w[t*3+1] + bb[t*3+1];
        dZ[t] = (x2 - mean) * rs * w[t*3+2] + bb[t*3+2];
    }
    __syncthreads();
}

// Final LN -> global.
__device__ __forceinline__ void layer_norm_out(const float* src, float* gout, int nrows,
                                               float inv_n, const float* w, const float* bb,
                                               float* red) {
    int t = threadIdx.x;
    float x0 = 0.f, x1 = 0.f, x2 = 0.f;
    if (t < nrows) { x0 = src[t*3]; x1 = src[t*3+1]; x2 = src[t*3+2]; }
    float s1 = x0 + x1 + x2;
    float s2 = fmaf(x0, x0, fmaf(x1, x1, x2 * x2));
    block_sum2(s1, s2, red);
    float mean = s1 * inv_n;
    float var  = fmaf(-mean, mean, s2 * inv_n);
    float rs = rsqrtf(var + 1e-5f);
    if (t < nrows) {
        gout[t*3+0] = (x0 - mean) * rs * w[t*3+0] + bb[t*3+0];
        gout[t*3+1] = (x1 - mean) * rs * w[t*3+1] + bb[t*3+1];
        gout[t*3+2] = (x2 - mean) * rs * w[t*3+2] + bb[t*3+2];
    }
}

__device__ __forceinline__ void proj3(const float* w, const float* bias,
                                      float x0, float x1, float x2,
                                      float& o0, float& o1, float& o2) {
    o0 = fmaf(w[0], x0, fmaf(w[1], x1, fmaf(w[2], x2, bias[0])));
    o1 = fmaf(w[3], x0, fmaf(w[4], x1, fmaf(w[5], x2, bias[1])));
    o2 = fmaf(w[6], x0, fmaf(w[7], x1, fmaf(w[8], x2, bias[2])));
}
__device__ __forceinline__ void proj3T(const float* w,
                                       float x0, float x1, float x2,
                                       float& o0, float& o1, float& o2) {
    o0 = fmaf(w[0], x0, fmaf(w[3], x1, w[6] * x2));
    o1 = fmaf(w[1], x0, fmaf(w[4], x1, w[7] * x2));
    o2 = fmaf(w[2], x0, fmaf(w[5], x1, w[8] * x2));
}
// q' = (Wk^T (Wq x + bq)) * C_SCALE; bk dropped (cancels in softmax)
__device__ __forceinline__ void make_q(const float* in_w, const float* in_b,
                                       float x0, float x1, float x2,
                                       float& q0, float& q1, float& q2) {
    float t0, t1, t2;
    proj3(in_w, in_b, x0, x1, x2, t0, t1, t2);
    proj3T(in_w + 9, t0, t1, t2, q0, q1, q2);
    q0 *= C_SCALE; q1 *= C_SCALE; q2 *= C_SCALE;
}

__device__ __forceinline__ void load_wff(float4* s_wff, const float* w1, const float* b1,
                                         const float* w2) {
    for (int h = threadIdx.x; h < HIDN; h += 256) {
        s_wff[2*h]   = make_float4(w1[h*3], w1[h*3+1], w1[h*3+2], b1[h]);
        s_wff[2*h+1] = make_float4(w2[h], w2[HIDN + h], w2[2*HIDN + h], 0.f);
    }
    __syncthreads();
}

// pos_enc row s: first 3 sin columns, invf[e] = 10000^(-2e/256)
__device__ __forceinline__ void pos3(int s, float& p0, float& p1, float& p2) {
    const float f1 = (float)0.93057204868496882;  // 10000^(-2/256)
    const float f2 = (float)0.86596432336006538;  // 10000^(-4/256)
    float a0 = (float)s;
    p0 = sinf(a0);
    p1 = sinf(a0 * f1);
    p2 = sinf(a0 * f2);
}

// One CTA = one batch. Grid caps occupancy at ~7 CTAs/SM.
__global__ void __launch_bounds__(256, 7)
fused_transformer_kernel(Params P) {
    // 16KB union s_U, time-multiplexed:
    //   attn: SoA keys (enc: sf[0..768), pT: sf[768..1152)) + partials s_U[320..576)
    //   ffn:  packed weights (2 float4/h), then FFN row-partials (after a sync)
    __shared__ __align__(16) float4 s_U[1024];
    __shared__ float s_x2[SIN * 3];
    __shared__ float s_R[SIN * 3];
    __shared__ float s_red[18];

    float* const sf = (float*)s_U;
    float* const sX = sf;            // 256 floats (enc keys / enc_out keys)
    float* const sY = sf + 256;
    float* const sZ = sf + 512;
    float* const pX = sf + 768;      // 128 floats (pT keys)
    float* const pY = sf + 896;
    float* const pZ = sf + 1024;
    float4* const s_part = s_U + 320;  // attn partials

    const int b    = blockIdx.x;
    const int t    = threadIdx.x;
    const int r128 = t & 127, half2 = t >> 7;
    const float INV768 = 1.0f / 768.0f;
    const float INV384 = 1.0f / 384.0f;

    float pe0, pe1, pe2;
    pos3(t, pe0, pe1, pe2);

    // ================= ENCODER =================
    // E1: pX = X + pos_enc -> SoA keys
    {
        const float* xr = P.X + ((size_t)b * SIN + t) * 3;
        sX[t] = xr[0] + pe0;
        sY[t] = xr[1] + pe1;
        sZ[t] = xr[2] + pe2;
    }
    __syncthreads();

    // E2: self-attention. 1 query (row t) x all 256 keys, packed f32x2.
    {
        float x0 = sX[t], x1 = sY[t], x2v = sZ[t];
        float q0, q1, q2;
        make_q(P.enc_in_w, P.enc_in_b, x0, x1, x2v, q0, q1, q2);
        u64 q0p = pack2(q0, q0), q1p = pack2(q1, q1), q2p = pack2(q2, q2);
        u64 aX = 0, aY = 0, aZ = 0, aL = 0;
        const double2* X2 = (const double2*)sX;
        const double2* Y2 = (const double2*)sY;
        const double2* Z2 = (const double2*)sZ;
        #pragma unroll 4
        for (int i = 0; i < 64; ++i) {
            double2 dx = X2[i], dy = Y2[i], dz = Z2[i];
            qstep(q0p, q1p, q2p,
                  __double_as_longlong(dx.x), __double_as_longlong(dy.x), __double_as_longlong(dz.x),
                  aX, aY, aZ, aL);
            qstep(q0p, q1p, q2p,
                  __double_as_longlong(dx.y), __double_as_longlong(dy.y), __double_as_longlong(dz.y),
                  aX, aY, aZ, aL);
        }
        float ax, ay, az, l;
        hsum4(aX, aY, aZ, aL, ax, ay, az, l);
        float inv = rcpf(l);
        float v0, v1, v2;
        proj3(P.enc_in_w + 18, P.enc_in_b + 6, ax*inv, ay*inv, az*inv, v0, v1, v2);
        float r0, r1, r2;
        proj3(P.enc_out_w, P.enc_out_b, v0, v1, v2, r0, r1, r2);
        s_R[t*3+0] = r0 + x0;
        s_R[t*3+1] = r1 + x1;
        s_R[t*3+2] = r2 + x2v;
    }
    __syncthreads();
    layer_norm(s_R, s_x2, SIN, INV768, P.enc_ln1_w, P.enc_ln1_b, s_red);

    // E3: FFN. 4 rows/thread {r, r+64, r+128, r+192} x 128 hidden (quarter hq).
    load_wff(s_U, P.enc_lin1_w, P.enc_lin1_b, P.enc_lin2_w);
    {
        const int r = t & 63, hq = t >> 6;
        float xr0[4], xr1[4], xr2[4];
        #pragma unroll
        for (int k = 0; k < 4; ++k) {
            int row = r + 64*k;
            xr0[k] = s_x2[row*3]; xr1[k] = s_x2[row*3+1]; xr2[k] = s_x2[row*3+2];
        }
        float a0[4] = {0.f,0.f,0.f,0.f}, a1[4] = {0.f,0.f,0.f,0.f}, a2[4] = {0.f,0.f,0.f,0.f};
        int h0 = hq * 128;
        #pragma unroll 2
        for (int h = h0; h < h0 + 128; ++h) {
            float4 w1 = s_U[2*h];
            float4 w2 = s_U[2*h+1];
            #pragma unroll
            for (int k = 0; k < 4; ++k) {
                float tk = fmaxf(fmaf(w1.x, xr0[k], fmaf(w1.y, xr1[k], fmaf(w1.z, xr2[k], w1.w))), 0.f);
                a0[k] = fmaf(tk, w2.x, a0[k]);
                a1[k] = fmaf(tk, w2.y, a1[k]);
                a2[k] = fmaf(tk, w2.z, a2[k]);
            }
        }
        __syncthreads();   // weights fully consumed; s_U becomes partial buffer
        #pragma unroll
        for (int k = 0; k < 4; ++k)
            s_U[hq*256 + r + 64*k] = make_float4(a0[k], a1[k], a2[k], 0.f);
    }
    __syncthreads();
    {
        float4 p0 = s_U[t], p1 = s_U[256+t], p2 = s_U[512+t], p3 = s_U[768+t];
        float eb0 = P.enc_lin2_b[0], eb1 = P.enc_lin2_b[1], eb2 = P.enc_lin2_b[2];
        s_R[t*3+0] = p0.x+p1.x+p2.x+p3.x + eb0 + s_x2[t*3+0];
        s_R[t*3+1] = p0.y+p1.y+p2.y+p3.y + eb1 + s_x2[t*3+1];
        s_R[t*3+2] = p0.z+p1.z+p2.z+p3.z + eb2 + s_x2[t*3+2];
    }
    __syncthreads();
    // LN2 -> enc_out straight into SoA key arrays (for cross-attn)
    layer_norm_soa(s_R, sX, sY, sZ, SIN, INV768, P.enc_ln2_w, P.enc_ln2_b, s_red);

    // ================= DECODER =================
    // D1: pT -> SoA (pX/pY/pZ)
    if (t < SPR) {
        const float* tr = P.T + ((size_t)b * SPR + t) * 3;
        pX[t] = tr[0] + pe0;
        pY[t] = tr[1] + pe1;
        pZ[t] = tr[2] + pe2;
    }
    __syncthreads();

    // D2: dec self-attn. query r128, keys [half2*64, +64), causal +1 mask.
    {
        int row = r128;
        float x0 = pX[row], x1 = pY[row], x2v = pZ[row];
        float q0, q1, q2;
        make_q(P.dec_a1_in_w, P.dec_a1_in_b, x0, x1, x2v, q0, q1, q2);
        u64 q0p = pack2(q0, q0), q1p = pack2(q1, q1), q2p = pack2(q2, q2);
        u64 aX = 0, aY = 0, aZ = 0, aL = 0;
        const double2* X2 = (const double2*)pX;
        const double2* Y2 = (const double2*)pY;
        const double2* Z2 = (const double2*)pZ;
        int i0 = half2 * 16;
        #pragma unroll 4
        for (int i = i0; i < i0 + 16; ++i) {
            int j = i * 4;
            double2 dx = X2[i], dy = Y2[i], dz = Z2[i];
            qstep_m(q0p, q1p, q2p,
                    __double_as_longlong(dx.x), __double_as_longlong(dy.x), __double_as_longlong(dz.x),
                    j, row, aX, aY, aZ, aL);
            qstep_m(q0p, q1p, q2p,
                    __double_as_longlong(dx.y), __double_as_longlong(dy.y), __double_as_longlong(dz.y),
                    j + 2, row, aX, aY, aZ, aL);
        }
        float ax, ay, az, l;
        hsum4(aX, aY, aZ, aL, ax, ay, az, l);
        s_part[row*2 + half2] = make_float4(l, ax, ay, az);
    }
    __syncthreads();
    if (t < SPR) {
        float4 pa = s_part[t*2], pb = s_part[t*2+1];
        float inv = rcpf(pa.x + pb.x);
        float v0, v1, v2;
        proj3(P.dec_a1_in_w + 18, P.dec_a1_in_b + 6,
              (pa.y+pb.y)*inv, (pa.z+pb.z)*inv, (pa.w+pb.w)*inv, v0, v1, v2);
        float r0, r1, r2;
        proj3(P.dec_a1_out_w, P.dec_a1_out_b, v0, v1, v2, r0, r1, r2);
        s_R[t*3+0] = r0 + pX[t];
        s_R[t*3+1] = r1 + pY[t];
        s_R[t*3+2] = r2 + pZ[t];
    }
    __syncthreads();
    layer_norm(s_R, s_x2, SPR, INV384, P.dec_ln1_w, P.dec_ln1_b, s_red);

    // D4: cross-attn. query r128 (x2), keys = enc_out SoA [half2*128, +128).
    {
        int row = r128;
        float q0, q1, q2;
        make_q(P.dec_a2_in_w, P.dec_a2_in_b,
               s_x2[row*3], s_x2[row*3+1], s_x2[row*3+2], q0, q1, q2);
        u64 q0p = pack2(q0, q0), q1p = pack2(q1, q1), q2p = pack2(q2, q2);
        u64 aX = 0, aY = 0, aZ = 0, aL = 0;
        const double2* X2 = (const double2*)sX;
        const double2* Y2 = (const double2*)sY;
        const double2* Z2 = (const double2*)sZ;
        int i0 = half2 * 32;
        #pragma unroll 4
        for (int i = i0; i < i0 + 32; ++i) {
            double2 dx = X2[i], dy = Y2[i], dz = Z2[i];
            qstep(q0p, q1p, q2p,
                  __double_as_longlong(dx.x), __double_as_longlong(dy.x), __double_as_longlong(dz.x),
                  aX, aY, aZ, aL);
            qstep(q0p, q1p, q2p,
                  __double_as_longlong(dx.y), __double_as_longlong(dy.y), __double_as_longlong(dz.y),
                  aX, aY, aZ, aL);
        }
        float ax, ay, az, l;
        hsum4(aX, aY, aZ, aL, ax, ay, az, l);
        s_part[row*2 + half2] = make_float4(l, ax, ay, az);
    }
    __syncthreads();
    if (t < SPR) {
        float4 pa = s_part[t*2], pb = s_part[t*2+1];
        float inv = rcpf(pa.x + pb.x);
        float v0, v1, v2;
        proj3(P.dec_a2_in_w + 18, P.dec_a2_in_b + 6,
              (pa.y+pb.y)*inv, (pa.z+pb.z)*inv, (pa.w+pb.w)*inv, v0, v1, v2);
        float r0, r1, r2;
        proj3(P.dec_a2_out_w, P.dec_a2_out_b, v0, v1, v2, r0, r1, r2);
        s_R[t*3+0] = r0 + s_x2[t*3+0];
        s_R[t*3+1] = r1 + s_x2[t*3+1];
        s_R[t*3+2] = r2 + s_x2[t*3+2];
    }
    __syncthreads();
    layer_norm(s_R, s_x2, SPR, INV384, P.dec_ln1_w, P.dec_ln1_b, s_red);  // x3

    // D5: dec FFN. 4 rows/thread {r, r+32, r+64, r+96} x 64 hidden (warp hw).
    load_wff(s_U, P.dec_lin1_w, P.dec_lin1_b, P.dec_lin2_w);
    {
        const int r = t & 31, hw = t >> 5;
        float xr0[4], xr1[4], xr2[4];
        #pragma unroll
        for (int k = 0; k < 4; ++k) {
            int row = r + 32*k;
            xr0[k] = s_x2[row*3]; xr1[k] = s_x2[row*3+1]; xr2[k] = s_x2[row*3+2];
        }
        float a0[4] = {0.f,0.f,0.f,0.f}, a1[4] = {0.f,0.f,0.f,0.f}, a2[4] = {0.f,0.f,0.f,0.f};
        int h0 = hw * 64;
        #pragma unroll 2
        for (int h = h0; h < h0 + 64; ++h) {
            float4 w1 = s_U[2*h];
            float4 w2 = s_U[2*h+1];
            #pragma unroll
            for (int k = 0; k < 4; ++k) {
                float tk = fmaxf(fmaf(w1.x, xr0[k], fmaf(w1.y, xr1[k], fmaf(w1.z, xr2[k], w1.w))), 0.f);
                a0[k] = fmaf(tk, w2.x, a0[k]);
                a1[k] = fmaf(tk, w2.y, a1[k]);
                a2[k] = fmaf(tk, w2.z, a2[k]);
            }
        }
        __syncthreads();   // weights consumed; s_U becomes partial buffer
        #pragma unroll
        for (int k = 0; k < 4; ++k)
            s_U[hw*128 + r + 32*k] = make_float4(a0[k], a1[k], a2[k], 0.f);
    }
    __syncthreads();
    if (t < SPR) {
        float s0 = 0.f, s1v = 0.f, s2v = 0.f;
        #pragma unroll
        for (int q = 0; q < 8; ++q) {
            float4 p = s_U[q*128 + t];
            s0 += p.x; s1v += p.y; s2v += p.z;
        }
        s_R[t*3+0] = s0 + P.dec_lin2_b[0] + s_x2[t*3+0];
        s_R[t*3+1] = s1v + P.dec_lin2_b[1] + s_x2[t*3+1];
        s_R[t*3+2] = s2v + P.dec_lin2_b[2] + s_x2[t*3+2];
    }
    __syncthreads();
    layer_norm_out(s_R, P.out + (size_t)b * SPR * 3, SPR, INV384,
                   P.dec_ln3_w, P.dec_ln3_b, s_red);
}

extern "C" void kernel_launch(void* const* d_in, const int* in_sizes, int n_in,
                              void* d_out, int out_size) {
    (void)in_sizes; (void)n_in; (void)out_size;
    Params P;
    P.X            = (const float*)d_in[0];
    P.T            = (const float*)d_in[1];
    P.enc_in_w     = (const float*)d_in[2];
    P.enc_in_b     = (const float*)d_in[3];
    P.enc_out_w    = (const float*)d_in[4];
    P.enc_out_b    = (const float*)d_in[5];
    P.enc_ln1_w    = (const float*)d_in[6];
    P.enc_ln1_b    = (const float*)d_in[7];
    P.enc_lin1_w   = (const float*)d_in[8];
    P.enc_lin1_b   = (const float*)d_in[9];
    P.enc_lin2_w   = (const float*)d_in[10];
    P.enc_lin2_b   = (const float*)d_in[11];
    P.enc_ln2_w    = (const float*)d_in[12];
    P.enc_ln2_b    = (const float*)d_in[13];
    P.dec_a1_in_w  = (const float*)d_in[14];
    P.dec_a1_in_b  = (const float*)d_in[15];
    P.dec_a1_out_w = (const float*)d_in[16];
    P.dec_a1_out_b = (const float*)d_in[17];
    P.dec_ln1_w    = (const float*)d_in[18];
    P.dec_ln1_b    = (const float*)d_in[19];
    P.dec_a2_in_w  = (const float*)d_in[20];
    P.dec_a2_in_b  = (const float*)d_in[21];
    P.dec_a2_out_w = (const float*)d_in[22];
    P.dec_a2_out_b = (const float*)d_in[23];
    P.dec_lin1_w   = (const float*)d_in[24];
    P.dec_lin1_b   = (const float*)d_in[25];
    P.dec_lin2_w   = (const float*)d_in[26];
    P.dec_lin2_b   = (const float*)d_in[27];
    P.dec_ln3_w    = (const float*)d_in[28];
    P.dec_ln3_b    = (const float*)d_in[29];
    P.out          = (float*)d_out;

    fused_transformer_kernel<<<NB, 256>>>(P);
}